// round 7
// baseline (speedup 1.0000x reference)
#include <cuda_runtime.h>
#include <cuda_fp16.h>

#define ERRF 1e-12f
constexpr int LEN = 2048;
constexpr int DIM = 64;
constexpr int NT  = 16;      // 16 j-tiles of 128
constexpr int BHN = 32;

// smem: A hi @0 (16K), A lo @16K, B double-buffer @32K (2 x 16K)
constexpr int OFF_ALO = 16384;
constexpr int OFF_B   = 32768;
constexpr int SMEM_TOTAL = 65536;

#define SWZ(o) ((o) ^ (((o) >> 3) & 0x70))

__device__ __forceinline__ unsigned smem_u32(const void* p) {
    return (unsigned)__cvta_generic_to_shared(p);
}
__device__ __forceinline__ float fast_lg2(float x) { float y; asm("lg2.approx.f32 %0, %1;" : "=f"(y) : "f"(x)); return y; }
__device__ __forceinline__ float fast_ex2(float x) { float y; asm("ex2.approx.f32 %0, %1;" : "=f"(y) : "f"(x)); return y; }
__device__ __forceinline__ float pow23(float x) {
    return fast_ex2(fast_lg2(fmaxf(x, 0.f) + ERRF) * 0.66666667f);
}

__device__ __forceinline__ void ldsm4(unsigned addr, unsigned& r0, unsigned& r1, unsigned& r2, unsigned& r3) {
    asm volatile("ldmatrix.sync.aligned.m8n8.x4.shared.b16 {%0,%1,%2,%3}, [%4];"
                 : "=r"(r0), "=r"(r1), "=r"(r2), "=r"(r3) : "r"(addr));
}

__device__ __forceinline__ void mma16816(float* c, unsigned a0, unsigned a1, unsigned a2, unsigned a3,
                                         unsigned b0, unsigned b1) {
    asm volatile("mma.sync.aligned.m16n8k16.row.col.f32.f16.f16.f32 "
                 "{%0,%1,%2,%3}, {%4,%5,%6,%7}, {%8,%9}, {%0,%1,%2,%3};"
                 : "+f"(c[0]), "+f"(c[1]), "+f"(c[2]), "+f"(c[3])
                 : "r"(a0), "r"(a1), "r"(a2), "r"(a3), "r"(b0), "r"(b1));
}

__device__ __forceinline__ unsigned pkh(float a, float b) {
    __half2 t = __floats2half2_rn(a, b);
    return *reinterpret_cast<unsigned*>(&t);
}

// B tile: 128 rows x 64 cols fp32 -> single fp16, K-major SW128 rows of 128B.
__device__ __forceinline__ void load_tile_b(const float* __restrict__ kb,
                                            const float* __restrict__ wv,
                                            int row0, char* smem, int off, int tid) {
    const int f4 = tid & 15;
    const int rg = tid >> 4;
    #pragma unroll
    for (int p = 0; p < 8; ++p) {
        int r = p * 16 + rg;
        float w = sqrtf(wv[row0 + r] + ERRF);
        float4 v = reinterpret_cast<const float4*>(kb + (size_t)(row0 + r) * DIM)[f4];
        unsigned o = SWZ((unsigned)(r * 128 + f4 * 8));
        *reinterpret_cast<uint2*>(smem + off + o) =
            make_uint2(pkh(v.x * w, v.y * w), pkh(v.z * w, v.w * w));
    }
}

// A tile: fp16 hi + lo split
__device__ __forceinline__ void load_tile_a(const float* __restrict__ kb,
                                            const float* __restrict__ wv,
                                            int row0, char* smem, int tid) {
    const int f4 = tid & 15;
    const int rg = tid >> 4;
    #pragma unroll
    for (int p = 0; p < 8; ++p) {
        int r = p * 16 + rg;
        float w = sqrtf(wv[row0 + r] + ERRF);
        float4 v = reinterpret_cast<const float4*>(kb + (size_t)(row0 + r) * DIM)[f4];
        float x0 = v.x * w, x1 = v.y * w, x2 = v.z * w, x3 = v.w * w;
        __half h0 = __float2half_rn(x0), h1 = __float2half_rn(x1);
        __half h2 = __float2half_rn(x2), h3 = __float2half_rn(x3);
        unsigned o = SWZ((unsigned)(r * 128 + f4 * 8));
        *reinterpret_cast<uint2*>(smem + o) = make_uint2(pkh(x0, x1), pkh(x2, x3));
        *reinterpret_cast<uint2*>(smem + OFF_ALO + o) =
            make_uint2(pkh(x0 - __half2float(h0), x1 - __half2float(h1)),
                       pkh(x2 - __half2float(h2), x3 - __half2float(h3)));
    }
}

__global__ void __launch_bounds__(256, 2)
mha_hmma3_kernel(const float* __restrict__ k, const float* __restrict__ src,
                 const float* __restrict__ dst, float* __restrict__ out)
{
    extern __shared__ char smem[];
    const int tid = threadIdx.x;
    const int wid = tid >> 5;
    const int lid = tid & 31;
    const int bh  = blockIdx.y;
    const int diag = blockIdx.x;          // j-tile index containing the diagonal
    const int it0 = blockIdx.x * 128;

    const float* kb = k   + (size_t)bh * LEN * DIM;
    const float* sb = src + (size_t)bh * LEN;
    const float* db = dst + (size_t)bh * LEN;
    float*       ob = out + (size_t)bh * LEN * LEN;

    load_tile_a(kb, sb, it0, smem, tid);
    load_tile_b(kb, db, 0, smem, OFF_B, tid);
    __syncthreads();

    // ldmatrix lane addressing (fp16, 128B K-major rows, SW128)
    const int l7  = lid & 7;
    const int sel = lid >> 3;
    const unsigned xk = (unsigned)(l7 << 4);
    const int arow  = wid * 16 + l7 + ((sel & 1) ? 8 : 0);
    const unsigned akoff = (sel & 2) ? 16u : 0u;
    const int bn    = l7 + ((sel & 2) ? 8 : 0);
    const unsigned bkoff = (sel & 1) ? 16u : 0u;
    const unsigned sbase = smem_u32(smem);
    const unsigned a_lane = sbase + (unsigned)(arow * 128);
    const unsigned b_lane = sbase + OFF_B + (unsigned)(bn * 128);

    // ---- A fragments: register-resident for the whole kernel ----
    unsigned ah[4][4], al[4][4];
    #pragma unroll
    for (int ks = 0; ks < 4; ++ks) {
        const unsigned ak = ((unsigned)(ks * 32) + akoff) ^ xk;
        ldsm4(a_lane + ak, ah[ks][0], ah[ks][1], ah[ks][2], ah[ks][3]);
        ldsm4(a_lane + OFF_ALO + ak, al[ks][0], al[ks][1], al[ks][2], al[ks][3]);
    }

    // epilogue lane mapping
    const int q  = lid & 3;
    const int g4 = lid >> 2;
    const int gi_lo = it0 + wid * 16 + g4;
    const int gi_hi = gi_lo + 8;
    float* const row_lo = ob + (size_t)gi_lo * LEN;
    float* const row_hi = ob + (size_t)gi_hi * LEN;

    float carry_lo = 0.f, carry_hi = 0.f;   // full row prefix (scan phase)
    float part_lo = 0.f,  part_hi = 0.f;    // lane-partial sums (below-diag phase)

    const int pf4 = tid & 15;
    const int prg = tid >> 4;

    for (int jt = 0; jt < NT; ++jt) {
        const int jb0 = jt * 128;
        const bool below = (jt < diag);

        // zero-fill stores for fully-masked tiles
        if (below) {
            const float4 z = make_float4(0.f, 0.f, 0.f, 0.f);
            float* base = ob + (size_t)(it0 + wid * 16) * LEN + jb0 + lid * 4;
            #pragma unroll
            for (int r = 0; r < 16; ++r)
                *reinterpret_cast<float4*>(base + (size_t)r * LEN) = z;
        }

        // ---- GEMM: 2-pass fp16 split (register-resident A, B from smem) ----
        float c[16][4];
        #pragma unroll
        for (int nb = 0; nb < 16; ++nb) {
            #pragma unroll
            for (int e = 0; e < 4; ++e) c[nb][e] = 0.f;
        }

        const unsigned bbuf = (unsigned)((jt & 1) * 16384);
        #pragma unroll
        for (int ks = 0; ks < 4; ++ks) {
            const unsigned bkb = ((unsigned)(ks * 32) + bkoff) ^ xk;
            #pragma unroll
            for (int np = 0; np < 8; ++np) {
                unsigned b0, b1, b2, b3;
                ldsm4(b_lane + bbuf + (unsigned)(np * 2048) + bkb, b0, b1, b2, b3);
                mma16816(c[np * 2],     ah[ks][0], ah[ks][1], ah[ks][2], ah[ks][3], b0, b1);
                mma16816(c[np * 2 + 1], ah[ks][0], ah[ks][1], ah[ks][2], ah[ks][3], b2, b3);
                mma16816(c[np * 2],     al[ks][0], al[ks][1], al[ks][2], al[ks][3], b0, b1);
                mma16816(c[np * 2 + 1], al[ks][0], al[ks][1], al[ks][2], al[ks][3], b2, b3);
            }
        }

        const int nxt = jt + 1;

        // convert lane-partials to full-row carry at the diagonal tile
        if (jt == diag) {
            float v = part_lo;
            v += __shfl_xor_sync(0xffffffffu, v, 1, 4);
            v += __shfl_xor_sync(0xffffffffu, v, 2, 4);
            carry_lo = v;
            v = part_hi;
            v += __shfl_xor_sync(0xffffffffu, v, 1, 4);
            v += __shfl_xor_sync(0xffffffffu, v, 2, 4);
            carry_hi = v;
        }

        // ---- batched epilogue: group of 4 nb blocks ----
        // stage 1: independent MUFU + quad scans + tot broadcasts
        // stage 2: short serial carry chain + stores
        auto scan_group = [&](int g, bool masked) {
            float u0l[4], u1l[4], totl[4], u0h[4], u1h[4], toth[4];
            #pragma unroll
            for (int m = 0; m < 4; ++m) {
                const int nb = g * 4 + m;
                {
                    float t0 = pow23(c[nb][0]);
                    float t1 = pow23(c[nb][1]);
                    float s = t0 + t1, p = s, o;
                    o = __shfl_up_sync(0xffffffffu, p, 1, 4); if (q >= 1) p += o;
                    o = __shfl_up_sync(0xffffffffu, p, 2, 4); if (q >= 2) p += o;
                    u0l[m] = t0 + (p - s);
                    u1l[m] = p;
                    totl[m] = __shfl_sync(0xffffffffu, p, 3, 4);
                }
                {
                    float t0 = pow23(c[nb][2]);
                    float t1 = pow23(c[nb][3]);
                    float s = t0 + t1, p = s, o;
                    o = __shfl_up_sync(0xffffffffu, p, 1, 4); if (q >= 1) p += o;
                    o = __shfl_up_sync(0xffffffffu, p, 2, 4); if (q >= 2) p += o;
                    u0h[m] = t0 + (p - s);
                    u1h[m] = p;
                    toth[m] = __shfl_sync(0xffffffffu, p, 3, 4);
                }
            }
            #pragma unroll
            for (int m = 0; m < 4; ++m) {
                const int nb = g * 4 + m;
                const int col0 = jb0 + nb * 8 + q * 2;
                {
                    float o0 = carry_lo + u0l[m], o1 = carry_lo + u1l[m];
                    carry_lo += totl[m];
                    float2 st = masked ? make_float2(col0 >= gi_lo ? o0 : 0.f,
                                                     col0 + 1 >= gi_lo ? o1 : 0.f)
                                       : make_float2(o0, o1);
                    *reinterpret_cast<float2*>(row_lo + col0) = st;
                }
                {
                    float o0 = carry_hi + u0h[m], o1 = carry_hi + u1h[m];
                    carry_hi += toth[m];
                    float2 st = masked ? make_float2(col0 >= gi_hi ? o0 : 0.f,
                                                     col0 + 1 >= gi_hi ? o1 : 0.f)
                                       : make_float2(o0, o1);
                    *reinterpret_cast<float2*>(row_hi + col0) = st;
                }
            }
        };

        auto accum_group = [&](int g) {
            #pragma unroll
            for (int m = 0; m < 4; ++m) {
                const int nb = g * 4 + m;
                part_lo += pow23(c[nb][0]) + pow23(c[nb][1]);
                part_hi += pow23(c[nb][2]) + pow23(c[nb][3]);
            }
        };

        // ---- first epilogue half (groups 0,1) ----
        if (below) {
            accum_group(0); accum_group(1);
        } else if (jt == diag) {
            scan_group(0, true); scan_group(1, true);
        } else {
            scan_group(0, false); scan_group(1, false);
        }

        // prefetch next B tile (LDG) between epilogue halves
        float4 pv[8]; float pw[8];
        if (nxt < NT) {
            #pragma unroll
            for (int p = 0; p < 8; ++p) {
                int r = p * 16 + prg;
                pv[p] = reinterpret_cast<const float4*>(kb + (size_t)(nxt * 128 + r) * DIM)[pf4];
                pw[p] = db[nxt * 128 + r];
            }
        }

        // ---- second epilogue half (groups 2,3) ----
        if (below) {
            accum_group(2); accum_group(3);
        } else if (jt == diag) {
            scan_group(2, true); scan_group(3, true);
        } else {
            scan_group(2, false); scan_group(3, false);
        }

        if (nxt < NT) {
            char* bdst = smem + OFF_B + (nxt & 1) * 16384;
            #pragma unroll
            for (int p = 0; p < 8; ++p) {
                int r = p * 16 + prg;
                float w = sqrtf(pw[p] + ERRF);
                unsigned o = SWZ((unsigned)(r * 128 + pf4 * 8));
                *reinterpret_cast<uint2*>(bdst + o) =
                    make_uint2(pkh(pv[p].x * w, pv[p].y * w), pkh(pv[p].z * w, pv[p].w * w));
            }
        }
        __syncthreads();
    }
}

extern "C" void kernel_launch(void* const* d_in, const int* in_sizes, int n_in,
                              void* d_out, int out_size) {
    const float* k   = (const float*)d_in[0];
    const float* src = (const float*)d_in[1];
    const float* dst = (const float*)d_in[2];
    float*       out = (float*)d_out;

    cudaFuncSetAttribute(mha_hmma3_kernel,
                         cudaFuncAttributeMaxDynamicSharedMemorySize, SMEM_TOTAL);
    (void)in_sizes; (void)n_in; (void)out_size;

    dim3 grid(LEN / 128, BHN);
    mha_hmma3_kernel<<<grid, 256, SMEM_TOTAL>>>(k, src, dst, out);
}

// round 8
// speedup vs baseline: 1.3252x; 1.3252x over previous
#include <cuda_runtime.h>
#include <cuda_fp16.h>

#define ERRF 1e-12f
constexpr int LEN = 2048;
constexpr int DIM = 64;
constexpr int NT  = 16;
constexpr int BHN = 32;

// Prepacked fp16 operands, row-major [bh][row][64], 128B per row.
__device__ __half g_Ah[BHN * LEN * DIM];   // k*sqrt(src)  hi
__device__ __half g_Al[BHN * LEN * DIM];   // k*sqrt(src)  lo
__device__ __half g_Bh[BHN * LEN * DIM];   // k*sqrt(dest) fp16

// smem: A hi @0 (16K), A lo @16K, B double-buffer @32K (2 x 16K)
constexpr int OFF_ALO = 16384;
constexpr int OFF_B   = 32768;
constexpr int SMEM_TOTAL = 65536;

#define SWZ(o) ((o) ^ (((o) >> 3) & 0x70))

__device__ __forceinline__ unsigned smem_u32(const void* p) {
    return (unsigned)__cvta_generic_to_shared(p);
}
__device__ __forceinline__ float fast_lg2(float x) { float y; asm("lg2.approx.f32 %0, %1;" : "=f"(y) : "f"(x)); return y; }
__device__ __forceinline__ float fast_ex2(float x) { float y; asm("ex2.approx.f32 %0, %1;" : "=f"(y) : "f"(x)); return y; }
__device__ __forceinline__ float pow23(float x) {
    return fast_ex2(fast_lg2(fmaxf(x, 0.f) + ERRF) * 0.66666667f);
}

__device__ __forceinline__ void ldsm4(unsigned addr, unsigned& r0, unsigned& r1, unsigned& r2, unsigned& r3) {
    asm volatile("ldmatrix.sync.aligned.m8n8.x4.shared.b16 {%0,%1,%2,%3}, [%4];"
                 : "=r"(r0), "=r"(r1), "=r"(r2), "=r"(r3) : "r"(addr));
}

__device__ __forceinline__ void mma16816(float* c, unsigned a0, unsigned a1, unsigned a2, unsigned a3,
                                         unsigned b0, unsigned b1) {
    asm volatile("mma.sync.aligned.m16n8k16.row.col.f32.f16.f16.f32 "
                 "{%0,%1,%2,%3}, {%4,%5,%6,%7}, {%8,%9}, {%0,%1,%2,%3};"
                 : "+f"(c[0]), "+f"(c[1]), "+f"(c[2]), "+f"(c[3])
                 : "r"(a0), "r"(a1), "r"(a2), "r"(a3), "r"(b0), "r"(b1));
}

__device__ __forceinline__ void cp16(unsigned sdst, const void* gsrc) {
    asm volatile("cp.async.cg.shared.global [%0], [%1], 16;" :: "r"(sdst), "l"(gsrc) : "memory");
}
__device__ __forceinline__ void cp_commit() { asm volatile("cp.async.commit_group;" ::: "memory"); }
__device__ __forceinline__ void cp_wait0()  { asm volatile("cp.async.wait_group 0;" ::: "memory"); }

// ---------------- prep kernel: fp32 -> scaled fp16 hi/lo ----------------
__global__ void __launch_bounds__(256)
prep_kernel(const float* __restrict__ k, const float* __restrict__ src,
            const float* __restrict__ dst)
{
    const int idx = blockIdx.x * 256 + threadIdx.x;   // 0 .. 262143 (quarter-rows)
    const int row = idx >> 2;                          // global row in [0, 65536)
    const int q   = idx & 3;                           // 16-element chunk within row
    const float ws = sqrtf(src[row] + ERRF);
    const float wd = sqrtf(dst[row] + ERRF);
    const float4* kp = reinterpret_cast<const float4*>(k + (size_t)row * DIM + q * 16);

    __half2 oh[8], ol[8], ob[8];
    #pragma unroll
    for (int p = 0; p < 4; ++p) {
        float4 v = kp[p];
        float a0 = v.x * ws, a1 = v.y * ws, a2 = v.z * ws, a3 = v.w * ws;
        __half h0 = __float2half_rn(a0), h1 = __float2half_rn(a1);
        __half h2 = __float2half_rn(a2), h3 = __float2half_rn(a3);
        oh[p * 2]     = __half2(h0, h1);
        oh[p * 2 + 1] = __half2(h2, h3);
        ol[p * 2]     = __floats2half2_rn(a0 - __half2float(h0), a1 - __half2float(h1));
        ol[p * 2 + 1] = __floats2half2_rn(a2 - __half2float(h2), a3 - __half2float(h3));
        ob[p * 2]     = __floats2half2_rn(v.x * wd, v.y * wd);
        ob[p * 2 + 1] = __floats2half2_rn(v.z * wd, v.w * wd);
    }
    const size_t o = (size_t)row * DIM + q * 16;
    uint4* dAh = reinterpret_cast<uint4*>(g_Ah + o);
    uint4* dAl = reinterpret_cast<uint4*>(g_Al + o);
    uint4* dBh = reinterpret_cast<uint4*>(g_Bh + o);
    const uint4* sh = reinterpret_cast<const uint4*>(oh);
    const uint4* sl = reinterpret_cast<const uint4*>(ol);
    const uint4* sb = reinterpret_cast<const uint4*>(ob);
    dAh[0] = sh[0]; dAh[1] = sh[1];
    dAl[0] = sl[0]; dAl[1] = sl[1];
    dBh[0] = sb[0]; dBh[1] = sb[1];
}

// copy one 16KB tile (128 rows x 128B) GMEM -> swizzled SMEM via cp.async
__device__ __forceinline__ void cp_tile(const char* gsrc, unsigned sdst, int tid) {
    #pragma unroll
    for (int i = 0; i < 4; ++i) {
        int cid = tid + 256 * i;            // 0..1023
        unsigned off = (unsigned)(cid << 4);
        cp16(sdst + SWZ(off), gsrc + off);
    }
}

// ---------------- main kernel ----------------
__global__ void __launch_bounds__(256, 2)
mha_hmma4_kernel(float* __restrict__ out)
{
    extern __shared__ char smem[];
    const int tid = threadIdx.x;
    const int wid = tid >> 5;
    const int lid = tid & 31;
    const int bh  = blockIdx.y;
    const int diag = blockIdx.x;
    const int it0 = blockIdx.x * 128;

    float* ob = out + (size_t)bh * LEN * LEN;
    const char* gA  = reinterpret_cast<const char*>(g_Ah + ((size_t)bh * LEN + it0) * DIM);
    const char* gAl = reinterpret_cast<const char*>(g_Al + ((size_t)bh * LEN + it0) * DIM);
    const char* gB  = reinterpret_cast<const char*>(g_Bh + (size_t)bh * LEN * DIM);

    const unsigned sbase = smem_u32(smem);

    // prologue: A hi, A lo, B tile 0 via cp.async
    cp_tile(gA,  sbase, tid);
    cp_tile(gAl, sbase + OFF_ALO, tid);
    cp_tile(gB,  sbase + OFF_B, tid);
    cp_commit();
    cp_wait0();
    __syncthreads();

    // ldmatrix lane addressing
    const int l7  = lid & 7;
    const int sel = lid >> 3;
    const unsigned xk = (unsigned)(l7 << 4);
    const int arow  = wid * 16 + l7 + ((sel & 1) ? 8 : 0);
    const unsigned akoff = (sel & 2) ? 16u : 0u;
    const int bn    = l7 + ((sel & 2) ? 8 : 0);
    const unsigned bkoff = (sel & 1) ? 16u : 0u;
    const unsigned a_lane = sbase + (unsigned)(arow * 128);
    const unsigned b_lane = sbase + OFF_B + (unsigned)(bn * 128);

    // A fragments register-resident (A smem never rewritten)
    unsigned ah[4][4], al[4][4];
    #pragma unroll
    for (int ks = 0; ks < 4; ++ks) {
        const unsigned ak = ((unsigned)(ks * 32) + akoff) ^ xk;
        ldsm4(a_lane + ak, ah[ks][0], ah[ks][1], ah[ks][2], ah[ks][3]);
        ldsm4(a_lane + OFF_ALO + ak, al[ks][0], al[ks][1], al[ks][2], al[ks][3]);
    }

    // epilogue lane mapping
    const int q  = lid & 3;
    const int g4 = lid >> 2;
    const int gi_lo = it0 + wid * 16 + g4;
    const int gi_hi = gi_lo + 8;
    float* const row_lo = ob + (size_t)gi_lo * LEN;
    float* const row_hi = ob + (size_t)gi_hi * LEN;

    float carry_lo = 0.f, carry_hi = 0.f;
    float part_lo = 0.f,  part_hi = 0.f;

    for (int jt = 0; jt < NT; ++jt) {
        const int jb0 = jt * 128;
        const bool below = (jt < diag);
        const int nxt = jt + 1;

        // async prefetch of next B tile — overlaps entire GEMM + epilogue
        if (nxt < NT) {
            cp_tile(gB + (size_t)nxt * 16384, sbase + OFF_B + (nxt & 1) * 16384, tid);
            cp_commit();
        }

        // zero-fill stores for fully-masked tiles
        if (below) {
            const float4 z = make_float4(0.f, 0.f, 0.f, 0.f);
            float* base = ob + (size_t)(it0 + wid * 16) * LEN + jb0 + lid * 4;
            #pragma unroll
            for (int r = 0; r < 16; ++r)
                *reinterpret_cast<float4*>(base + (size_t)r * LEN) = z;
        }

        // ---- GEMM: 2-pass fp16 split (A in regs, B from smem) ----
        float c[16][4];
        #pragma unroll
        for (int nb = 0; nb < 16; ++nb) {
            #pragma unroll
            for (int e = 0; e < 4; ++e) c[nb][e] = 0.f;
        }

        const unsigned bbuf = (unsigned)((jt & 1) * 16384);
        #pragma unroll
        for (int ks = 0; ks < 4; ++ks) {
            const unsigned bkb = ((unsigned)(ks * 32) + bkoff) ^ xk;
            #pragma unroll
            for (int np = 0; np < 8; ++np) {
                unsigned b0, b1, b2, b3;
                ldsm4(b_lane + bbuf + (unsigned)(np * 2048) + bkb, b0, b1, b2, b3);
                mma16816(c[np * 2],     ah[ks][0], ah[ks][1], ah[ks][2], ah[ks][3], b0, b1);
                mma16816(c[np * 2 + 1], ah[ks][0], ah[ks][1], ah[ks][2], ah[ks][3], b2, b3);
                mma16816(c[np * 2],     al[ks][0], al[ks][1], al[ks][2], al[ks][3], b0, b1);
                mma16816(c[np * 2 + 1], al[ks][0], al[ks][1], al[ks][2], al[ks][3], b2, b3);
            }
        }

        // lane-partials -> full-row carry at the diagonal tile
        if (jt == diag) {
            float v = part_lo;
            v += __shfl_xor_sync(0xffffffffu, v, 1, 4);
            v += __shfl_xor_sync(0xffffffffu, v, 2, 4);
            carry_lo = v;
            v = part_hi;
            v += __shfl_xor_sync(0xffffffffu, v, 1, 4);
            v += __shfl_xor_sync(0xffffffffu, v, 2, 4);
            carry_hi = v;
        }

        auto scan_store = [&](int nb, bool masked) {
            const int col0 = jb0 + nb * 8 + q * 2;
            {
                float t0 = pow23(c[nb][0]);
                float t1 = pow23(c[nb][1]);
                float s = t0 + t1, p = s, o;
                o = __shfl_up_sync(0xffffffffu, p, 1, 4); if (q >= 1) p += o;
                o = __shfl_up_sync(0xffffffffu, p, 2, 4); if (q >= 2) p += o;
                float tot  = __shfl_sync(0xffffffffu, p, 3, 4);
                float excl = carry_lo + p - s;
                float o0 = excl + t0, o1 = excl + s;
                carry_lo += tot;
                float2 st = masked ? make_float2(col0 >= gi_lo ? o0 : 0.f,
                                                 col0 + 1 >= gi_lo ? o1 : 0.f)
                                   : make_float2(o0, o1);
                *reinterpret_cast<float2*>(row_lo + col0) = st;
            }
            {
                float t0 = pow23(c[nb][2]);
                float t1 = pow23(c[nb][3]);
                float s = t0 + t1, p = s, o;
                o = __shfl_up_sync(0xffffffffu, p, 1, 4); if (q >= 1) p += o;
                o = __shfl_up_sync(0xffffffffu, p, 2, 4); if (q >= 2) p += o;
                float tot  = __shfl_sync(0xffffffffu, p, 3, 4);
                float excl = carry_hi + p - s;
                float o0 = excl + t0, o1 = excl + s;
                carry_hi += tot;
                float2 st = masked ? make_float2(col0 >= gi_hi ? o0 : 0.f,
                                                 col0 + 1 >= gi_hi ? o1 : 0.f)
                                   : make_float2(o0, o1);
                *reinterpret_cast<float2*>(row_hi + col0) = st;
            }
        };

        auto accum_only = [&](int nb) {
            part_lo += pow23(c[nb][0]) + pow23(c[nb][1]);
            part_hi += pow23(c[nb][2]) + pow23(c[nb][3]);
        };

        if (below) {
            #pragma unroll
            for (int nb = 0; nb < 16; ++nb) accum_only(nb);
        } else if (jt == diag) {
            #pragma unroll
            for (int nb = 0; nb < 16; ++nb) scan_store(nb, true);
        } else {
            #pragma unroll
            for (int nb = 0; nb < 16; ++nb) scan_store(nb, false);
        }

        if (nxt < NT) cp_wait0();
        __syncthreads();
    }
}

extern "C" void kernel_launch(void* const* d_in, const int* in_sizes, int n_in,
                              void* d_out, int out_size) {
    const float* k   = (const float*)d_in[0];
    const float* src = (const float*)d_in[1];
    const float* dst = (const float*)d_in[2];
    float*       out = (float*)d_out;

    cudaFuncSetAttribute(mha_hmma4_kernel,
                         cudaFuncAttributeMaxDynamicSharedMemorySize, SMEM_TOTAL);
    (void)in_sizes; (void)n_in; (void)out_size;

    prep_kernel<<<BHN * LEN * 4 / 256, 256>>>(k, src, dst);
    dim3 grid(LEN / 128, BHN);
    mha_hmma4_kernel<<<grid, 256, SMEM_TOTAL>>>(out);
}

// round 9
// speedup vs baseline: 1.3970x; 1.0542x over previous
#include <cuda_runtime.h>
#include <cuda_fp16.h>

#define ERRF 1e-12f
constexpr int LEN = 2048;
constexpr int DIM = 64;
constexpr int NT  = 16;
constexpr int BHN = 32;

// Prepacked fp16 operands, row-major [bh][row][64], 128B per row.
__device__ __half g_Ah[BHN * LEN * DIM];   // k*sqrt(src)  hi
__device__ __half g_Al[BHN * LEN * DIM];   // k*sqrt(src)  lo
__device__ __half g_Bh[BHN * LEN * DIM];   // k*sqrt(dest) fp16

// smem: A hi @0 (16K), A lo @16K, B double-buffer @32K (2 x 16K)
constexpr int OFF_ALO = 16384;
constexpr int OFF_B   = 32768;
constexpr int SMEM_TOTAL = 65536;

#define SWZ(o) ((o) ^ (((o) >> 3) & 0x70))

__device__ __forceinline__ unsigned smem_u32(const void* p) {
    return (unsigned)__cvta_generic_to_shared(p);
}
__device__ __forceinline__ float fast_lg2(float x) { float y; asm("lg2.approx.f32 %0, %1;" : "=f"(y) : "f"(x)); return y; }
__device__ __forceinline__ float fast_ex2(float x) { float y; asm("ex2.approx.f32 %0, %1;" : "=f"(y) : "f"(x)); return y; }
__device__ __forceinline__ float pow23(float x) {
    return fast_ex2(fast_lg2(fmaxf(x, 0.f) + ERRF) * 0.66666667f);
}

__device__ __forceinline__ void ldsm4(unsigned addr, unsigned& r0, unsigned& r1, unsigned& r2, unsigned& r3) {
    asm volatile("ldmatrix.sync.aligned.m8n8.x4.shared.b16 {%0,%1,%2,%3}, [%4];"
                 : "=r"(r0), "=r"(r1), "=r"(r2), "=r"(r3) : "r"(addr));
}

__device__ __forceinline__ void mma16816(float* c, unsigned a0, unsigned a1, unsigned a2, unsigned a3,
                                         unsigned b0, unsigned b1) {
    asm volatile("mma.sync.aligned.m16n8k16.row.col.f32.f16.f16.f32 "
                 "{%0,%1,%2,%3}, {%4,%5,%6,%7}, {%8,%9}, {%0,%1,%2,%3};"
                 : "+f"(c[0]), "+f"(c[1]), "+f"(c[2]), "+f"(c[3])
                 : "r"(a0), "r"(a1), "r"(a2), "r"(a3), "r"(b0), "r"(b1));
}

__device__ __forceinline__ void cp16(unsigned sdst, const void* gsrc) {
    asm volatile("cp.async.cg.shared.global [%0], [%1], 16;" :: "r"(sdst), "l"(gsrc) : "memory");
}
__device__ __forceinline__ void cp_commit() { asm volatile("cp.async.commit_group;" ::: "memory"); }
__device__ __forceinline__ void cp_wait0()  { asm volatile("cp.async.wait_group 0;" ::: "memory"); }

// ---------------- prep kernel: fp32 -> scaled fp16 hi/lo ----------------
__global__ void __launch_bounds__(256)
prep_kernel(const float* __restrict__ k, const float* __restrict__ src,
            const float* __restrict__ dst)
{
    const int idx = blockIdx.x * 256 + threadIdx.x;
    const int row = idx >> 2;
    const int q   = idx & 3;
    const float ws = sqrtf(src[row] + ERRF);
    const float wd = sqrtf(dst[row] + ERRF);
    const float4* kp = reinterpret_cast<const float4*>(k + (size_t)row * DIM + q * 16);

    __half2 oh[8], ol[8], ob[8];
    #pragma unroll
    for (int p = 0; p < 4; ++p) {
        float4 v = kp[p];
        float a0 = v.x * ws, a1 = v.y * ws, a2 = v.z * ws, a3 = v.w * ws;
        __half h0 = __float2half_rn(a0), h1 = __float2half_rn(a1);
        __half h2 = __float2half_rn(a2), h3 = __float2half_rn(a3);
        oh[p * 2]     = __half2(h0, h1);
        oh[p * 2 + 1] = __half2(h2, h3);
        ol[p * 2]     = __floats2half2_rn(a0 - __half2float(h0), a1 - __half2float(h1));
        ol[p * 2 + 1] = __floats2half2_rn(a2 - __half2float(h2), a3 - __half2float(h3));
        ob[p * 2]     = __floats2half2_rn(v.x * wd, v.y * wd);
        ob[p * 2 + 1] = __floats2half2_rn(v.z * wd, v.w * wd);
    }
    const size_t o = (size_t)row * DIM + q * 16;
    uint4* dAh = reinterpret_cast<uint4*>(g_Ah + o);
    uint4* dAl = reinterpret_cast<uint4*>(g_Al + o);
    uint4* dBh = reinterpret_cast<uint4*>(g_Bh + o);
    const uint4* sh = reinterpret_cast<const uint4*>(oh);
    const uint4* sl = reinterpret_cast<const uint4*>(ol);
    const uint4* sb = reinterpret_cast<const uint4*>(ob);
    dAh[0] = sh[0]; dAh[1] = sh[1];
    dAl[0] = sl[0]; dAl[1] = sl[1];
    dBh[0] = sb[0]; dBh[1] = sb[1];
}

// copy one 16KB tile (128 rows x 128B) GMEM -> swizzled SMEM via cp.async
__device__ __forceinline__ void cp_tile(const char* gsrc, unsigned sdst, int tid) {
    #pragma unroll
    for (int i = 0; i < 4; ++i) {
        int cid = tid + 256 * i;
        unsigned off = (unsigned)(cid << 4);
        cp16(sdst + SWZ(off), gsrc + off);
    }
}

// ---------------- main kernel ----------------
__global__ void __launch_bounds__(256, 2)
mha_hmma5_kernel(float* __restrict__ out)
{
    extern __shared__ char smem[];
    const int tid = threadIdx.x;
    const int wid = tid >> 5;
    const int lid = tid & 31;
    const int bh  = blockIdx.y;
    const int diag = blockIdx.x;
    const int it0 = blockIdx.x * 128;

    float* ob = out + (size_t)bh * LEN * LEN;
    const char* gA  = reinterpret_cast<const char*>(g_Ah + ((size_t)bh * LEN + it0) * DIM);
    const char* gAl = reinterpret_cast<const char*>(g_Al + ((size_t)bh * LEN + it0) * DIM);
    const char* gB  = reinterpret_cast<const char*>(g_Bh + (size_t)bh * LEN * DIM);

    const unsigned sbase = smem_u32(smem);

    // prologue: A hi, A lo, B tile 0 via cp.async
    cp_tile(gA,  sbase, tid);
    cp_tile(gAl, sbase + OFF_ALO, tid);
    cp_tile(gB,  sbase + OFF_B, tid);
    cp_commit();
    cp_wait0();
    __syncthreads();

    // ldmatrix lane addressing
    const int l7  = lid & 7;
    const int sel = lid >> 3;
    const unsigned xk = (unsigned)(l7 << 4);
    const int arow  = wid * 16 + l7 + ((sel & 1) ? 8 : 0);
    const unsigned akoff = (sel & 2) ? 16u : 0u;
    const int bn    = l7 + ((sel & 2) ? 8 : 0);
    const unsigned bkoff = (sel & 1) ? 16u : 0u;
    const unsigned a_lane = sbase + (unsigned)(arow * 128);
    const unsigned b_lane = sbase + OFF_B + (unsigned)(bn * 128);

    // A fragments register-resident
    unsigned ah[4][4], al[4][4];
    #pragma unroll
    for (int ks = 0; ks < 4; ++ks) {
        const unsigned ak = ((unsigned)(ks * 32) + akoff) ^ xk;
        ldsm4(a_lane + ak, ah[ks][0], ah[ks][1], ah[ks][2], ah[ks][3]);
        ldsm4(a_lane + OFF_ALO + ak, al[ks][0], al[ks][1], al[ks][2], al[ks][3]);
    }

    // epilogue lane mapping
    const int q  = lid & 3;
    const int g4 = lid >> 2;
    const int gi_lo = it0 + wid * 16 + g4;
    const int gi_hi = gi_lo + 8;
    float* const row_lo = ob + (size_t)gi_lo * LEN;
    float* const row_hi = ob + (size_t)gi_hi * LEN;

    float carry_lo = 0.f, carry_hi = 0.f;
    float part_lo = 0.f,  part_hi = 0.f;

    for (int jt = 0; jt < NT; ++jt) {
        const int jb0 = jt * 128;
        const bool below = (jt < diag);
        const int nxt = jt + 1;

        // async prefetch of next B tile — overlaps GEMM + epilogue
        if (nxt < NT) {
            cp_tile(gB + (size_t)nxt * 16384, sbase + OFF_B + (nxt & 1) * 16384, tid);
            cp_commit();
        }

        // zero-fill stores for fully-masked tiles
        if (below) {
            const float4 z = make_float4(0.f, 0.f, 0.f, 0.f);
            float* base = ob + (size_t)(it0 + wid * 16) * LEN + jb0 + lid * 4;
            #pragma unroll
            for (int r = 0; r < 16; ++r)
                *reinterpret_cast<float4*>(base + (size_t)r * LEN) = z;
        }

        float c[16][4];
        #pragma unroll
        for (int nb = 0; nb < 16; ++nb) {
            #pragma unroll
            for (int e = 0; e < 4; ++e) c[nb][e] = 0.f;
        }

        const unsigned bbuf = (unsigned)((jt & 1) * 16384);
        if (below) {
            // carry-only tile: single-pass fp16 (hi only) — precision headroom is 50x
            #pragma unroll
            for (int ks = 0; ks < 4; ++ks) {
                const unsigned bkb = ((unsigned)(ks * 32) + bkoff) ^ xk;
                #pragma unroll
                for (int np = 0; np < 8; ++np) {
                    unsigned b0, b1, b2, b3;
                    ldsm4(b_lane + bbuf + (unsigned)(np * 2048) + bkb, b0, b1, b2, b3);
                    mma16816(c[np * 2],     ah[ks][0], ah[ks][1], ah[ks][2], ah[ks][3], b0, b1);
                    mma16816(c[np * 2 + 1], ah[ks][0], ah[ks][1], ah[ks][2], ah[ks][3], b2, b3);
                }
            }
        } else {
            // visible tile: 2-pass fp16 split
            #pragma unroll
            for (int ks = 0; ks < 4; ++ks) {
                const unsigned bkb = ((unsigned)(ks * 32) + bkoff) ^ xk;
                #pragma unroll
                for (int np = 0; np < 8; ++np) {
                    unsigned b0, b1, b2, b3;
                    ldsm4(b_lane + bbuf + (unsigned)(np * 2048) + bkb, b0, b1, b2, b3);
                    mma16816(c[np * 2],     ah[ks][0], ah[ks][1], ah[ks][2], ah[ks][3], b0, b1);
                    mma16816(c[np * 2 + 1], ah[ks][0], ah[ks][1], ah[ks][2], ah[ks][3], b2, b3);
                    mma16816(c[np * 2],     al[ks][0], al[ks][1], al[ks][2], al[ks][3], b0, b1);
                    mma16816(c[np * 2 + 1], al[ks][0], al[ks][1], al[ks][2], al[ks][3], b2, b3);
                }
            }
        }

        // lane-partials -> full-row carry at the diagonal tile
        if (jt == diag) {
            float v = part_lo;
            v += __shfl_xor_sync(0xffffffffu, v, 1, 4);
            v += __shfl_xor_sync(0xffffffffu, v, 2, 4);
            carry_lo = v;
            v = part_hi;
            v += __shfl_xor_sync(0xffffffffu, v, 1, 4);
            v += __shfl_xor_sync(0xffffffffu, v, 2, 4);
            carry_hi = v;
        }

        auto scan_store = [&](int nb, bool masked) {
            const int col0 = jb0 + nb * 8 + q * 2;
            {
                float t0 = pow23(c[nb][0]);
                float t1 = pow23(c[nb][1]);
                float s = t0 + t1, p = s, o;
                o = __shfl_up_sync(0xffffffffu, p, 1, 4); if (q >= 1) p += o;
                o = __shfl_up_sync(0xffffffffu, p, 2, 4); if (q >= 2) p += o;
                float tot  = __shfl_sync(0xffffffffu, p, 3, 4);
                float excl = carry_lo + p - s;
                float o0 = excl + t0, o1 = excl + s;
                carry_lo += tot;
                float2 st = masked ? make_float2(col0 >= gi_lo ? o0 : 0.f,
                                                 col0 + 1 >= gi_lo ? o1 : 0.f)
                                   : make_float2(o0, o1);
                *reinterpret_cast<float2*>(row_lo + col0) = st;
            }
            {
                float t0 = pow23(c[nb][2]);
                float t1 = pow23(c[nb][3]);
                float s = t0 + t1, p = s, o;
                o = __shfl_up_sync(0xffffffffu, p, 1, 4); if (q >= 1) p += o;
                o = __shfl_up_sync(0xffffffffu, p, 2, 4); if (q >= 2) p += o;
                float tot  = __shfl_sync(0xffffffffu, p, 3, 4);
                float excl = carry_hi + p - s;
                float o0 = excl + t0, o1 = excl + s;
                carry_hi += tot;
                float2 st = masked ? make_float2(col0 >= gi_hi ? o0 : 0.f,
                                                 col0 + 1 >= gi_hi ? o1 : 0.f)
                                   : make_float2(o0, o1);
                *reinterpret_cast<float2*>(row_hi + col0) = st;
            }
        };

        auto accum_only = [&](int nb) {
            part_lo += pow23(c[nb][0]) + pow23(c[nb][1]);
            part_hi += pow23(c[nb][2]) + pow23(c[nb][3]);
        };

        if (below) {
            #pragma unroll
            for (int nb = 0; nb < 16; ++nb) accum_only(nb);
        } else if (jt == diag) {
            #pragma unroll
            for (int nb = 0; nb < 16; ++nb) scan_store(nb, true);
        } else {
            #pragma unroll
            for (int nb = 0; nb < 16; ++nb) scan_store(nb, false);
        }

        if (nxt < NT) cp_wait0();
        __syncthreads();
    }
}

extern "C" void kernel_launch(void* const* d_in, const int* in_sizes, int n_in,
                              void* d_out, int out_size) {
    const float* k   = (const float*)d_in[0];
    const float* src = (const float*)d_in[1];
    const float* dst = (const float*)d_in[2];
    float*       out = (float*)d_out;

    cudaFuncSetAttribute(mha_hmma5_kernel,
                         cudaFuncAttributeMaxDynamicSharedMemorySize, SMEM_TOTAL);
    (void)in_sizes; (void)n_in; (void)out_size;

    prep_kernel<<<BHN * LEN * 4 / 256, 256>>>(k, src, dst);
    dim3 grid(LEN / 128, BHN);
    mha_hmma5_kernel<<<grid, 256, SMEM_TOTAL>>>(out);
}

// round 10
// speedup vs baseline: 1.5332x; 1.0976x over previous
#include <cuda_runtime.h>
#include <cuda_fp16.h>

#define ERRF 1e-12f
constexpr int LEN = 2048;
constexpr int DIM = 64;
constexpr int NT  = 16;
constexpr int BHN = 32;

// Prepacked fp16 operands, row-major [bh][row][64], 128B per row.
__device__ __half g_Ah[BHN * LEN * DIM];   // k*sqrt(src)  hi
__device__ __half g_Al[BHN * LEN * DIM];   // k*sqrt(src)  lo
__device__ __half g_Bh[BHN * LEN * DIM];   // k*sqrt(dest) fp16

// smem: A hi @0 (8K), A lo @8K, B double-buffer @16K (2 x 16K)
constexpr int OFF_ALO = 8192;
constexpr int OFF_B   = 16384;
constexpr int SMEM_TOTAL = 49152;   // 48 KB -> 4 CTAs/SM

#define SWZ(o) ((o) ^ (((o) >> 3) & 0x70))

__device__ __forceinline__ unsigned smem_u32(const void* p) {
    return (unsigned)__cvta_generic_to_shared(p);
}
__device__ __forceinline__ float fast_lg2(float x) { float y; asm("lg2.approx.f32 %0, %1;" : "=f"(y) : "f"(x)); return y; }
__device__ __forceinline__ float fast_ex2(float x) { float y; asm("ex2.approx.f32 %0, %1;" : "=f"(y) : "f"(x)); return y; }
__device__ __forceinline__ float pow23(float x) {
    return fast_ex2(fast_lg2(fmaxf(x, 0.f) + ERRF) * 0.66666667f);
}

__device__ __forceinline__ void ldsm4(unsigned addr, unsigned& r0, unsigned& r1, unsigned& r2, unsigned& r3) {
    asm volatile("ldmatrix.sync.aligned.m8n8.x4.shared.b16 {%0,%1,%2,%3}, [%4];"
                 : "=r"(r0), "=r"(r1), "=r"(r2), "=r"(r3) : "r"(addr));
}

__device__ __forceinline__ void mma16816(float* c, unsigned a0, unsigned a1, unsigned a2, unsigned a3,
                                         unsigned b0, unsigned b1) {
    asm volatile("mma.sync.aligned.m16n8k16.row.col.f32.f16.f16.f32 "
                 "{%0,%1,%2,%3}, {%4,%5,%6,%7}, {%8,%9}, {%0,%1,%2,%3};"
                 : "+f"(c[0]), "+f"(c[1]), "+f"(c[2]), "+f"(c[3])
                 : "r"(a0), "r"(a1), "r"(a2), "r"(a3), "r"(b0), "r"(b1));
}

__device__ __forceinline__ void cp16(unsigned sdst, const void* gsrc) {
    asm volatile("cp.async.cg.shared.global [%0], [%1], 16;" :: "r"(sdst), "l"(gsrc) : "memory");
}
__device__ __forceinline__ void cp_commit() { asm volatile("cp.async.commit_group;" ::: "memory"); }
__device__ __forceinline__ void cp_wait0()  { asm volatile("cp.async.wait_group 0;" ::: "memory"); }

// ---------------- prep kernel: fp32 -> scaled fp16 hi/lo ----------------
__global__ void __launch_bounds__(256)
prep_kernel(const float* __restrict__ k, const float* __restrict__ src,
            const float* __restrict__ dst)
{
    const int idx = blockIdx.x * 256 + threadIdx.x;
    const int row = idx >> 2;
    const int q   = idx & 3;
    const float ws = sqrtf(src[row] + ERRF);
    const float wd = sqrtf(dst[row] + ERRF);
    const float4* kp = reinterpret_cast<const float4*>(k + (size_t)row * DIM + q * 16);

    __half2 oh[8], ol[8], ob[8];
    #pragma unroll
    for (int p = 0; p < 4; ++p) {
        float4 v = kp[p];
        float a0 = v.x * ws, a1 = v.y * ws, a2 = v.z * ws, a3 = v.w * ws;
        __half h0 = __float2half_rn(a0), h1 = __float2half_rn(a1);
        __half h2 = __float2half_rn(a2), h3 = __float2half_rn(a3);
        oh[p * 2]     = __half2(h0, h1);
        oh[p * 2 + 1] = __half2(h2, h3);
        ol[p * 2]     = __floats2half2_rn(a0 - __half2float(h0), a1 - __half2float(h1));
        ol[p * 2 + 1] = __floats2half2_rn(a2 - __half2float(h2), a3 - __half2float(h3));
        ob[p * 2]     = __floats2half2_rn(v.x * wd, v.y * wd);
        ob[p * 2 + 1] = __floats2half2_rn(v.z * wd, v.w * wd);
    }
    const size_t o = (size_t)row * DIM + q * 16;
    uint4* dAh = reinterpret_cast<uint4*>(g_Ah + o);
    uint4* dAl = reinterpret_cast<uint4*>(g_Al + o);
    uint4* dBh = reinterpret_cast<uint4*>(g_Bh + o);
    const uint4* sh = reinterpret_cast<const uint4*>(oh);
    const uint4* sl = reinterpret_cast<const uint4*>(ol);
    const uint4* sb = reinterpret_cast<const uint4*>(ob);
    dAh[0] = sh[0]; dAh[1] = sh[1];
    dAl[0] = sl[0]; dAl[1] = sl[1];
    dBh[0] = sb[0]; dBh[1] = sb[1];
}

// copy one 16KB B tile GMEM -> swizzled SMEM via cp.async (128 threads)
__device__ __forceinline__ void cp_tile16(const char* gsrc, unsigned sdst, int tid) {
    #pragma unroll
    for (int i = 0; i < 8; ++i) {
        int cid = tid + 128 * i;            // 0..1023
        unsigned off = (unsigned)(cid << 4);
        cp16(sdst + SWZ(off), gsrc + off);
    }
}
// copy one 8KB A tile (64 rows) GMEM -> swizzled SMEM
__device__ __forceinline__ void cp_tile8(const char* gsrc, unsigned sdst, int tid) {
    #pragma unroll
    for (int i = 0; i < 4; ++i) {
        int cid = tid + 128 * i;            // 0..511
        unsigned off = (unsigned)(cid << 4);
        cp16(sdst + SWZ(off), gsrc + off);
    }
}

// ---------------- main kernel: 128 threads, 64-row i-tile ----------------
__global__ void __launch_bounds__(128, 4)
mha_hmma6_kernel(float* __restrict__ out)
{
    extern __shared__ char smem[];
    const int tid = threadIdx.x;
    const int wid = tid >> 5;              // 0..3
    const int lid = tid & 31;
    const int bh  = blockIdx.y;
    const int diag = blockIdx.x >> 1;      // j-tile index containing the diagonal
    const int it0 = blockIdx.x * 64;

    float* ob = out + (size_t)bh * LEN * LEN;
    const char* gA  = reinterpret_cast<const char*>(g_Ah + ((size_t)bh * LEN + it0) * DIM);
    const char* gAl = reinterpret_cast<const char*>(g_Al + ((size_t)bh * LEN + it0) * DIM);
    const char* gB  = reinterpret_cast<const char*>(g_Bh + (size_t)bh * LEN * DIM);

    const unsigned sbase = smem_u32(smem);

    // prologue: A hi, A lo (8KB each), B tile 0 via cp.async
    cp_tile8(gA,  sbase, tid);
    cp_tile8(gAl, sbase + OFF_ALO, tid);
    cp_tile16(gB, sbase + OFF_B, tid);
    cp_commit();
    cp_wait0();
    __syncthreads();

    // ldmatrix lane addressing
    const int l7  = lid & 7;
    const int sel = lid >> 3;
    const unsigned xk = (unsigned)(l7 << 4);
    const int arow  = wid * 16 + l7 + ((sel & 1) ? 8 : 0);
    const unsigned akoff = (sel & 2) ? 16u : 0u;
    const int bn    = l7 + ((sel & 2) ? 8 : 0);
    const unsigned bkoff = (sel & 1) ? 16u : 0u;
    const unsigned a_lane = sbase + (unsigned)(arow * 128);
    const unsigned b_lane = sbase + OFF_B + (unsigned)(bn * 128);

    // A fragments register-resident
    unsigned ah[4][4], al[4][4];
    #pragma unroll
    for (int ks = 0; ks < 4; ++ks) {
        const unsigned ak = ((unsigned)(ks * 32) + akoff) ^ xk;
        ldsm4(a_lane + ak, ah[ks][0], ah[ks][1], ah[ks][2], ah[ks][3]);
        ldsm4(a_lane + OFF_ALO + ak, al[ks][0], al[ks][1], al[ks][2], al[ks][3]);
    }

    // epilogue lane mapping
    const int q  = lid & 3;
    const int g4 = lid >> 2;
    const int gi_lo = it0 + wid * 16 + g4;
    const int gi_hi = gi_lo + 8;
    float* const row_lo = ob + (size_t)gi_lo * LEN;
    float* const row_hi = ob + (size_t)gi_hi * LEN;

    float carry_lo = 0.f, carry_hi = 0.f;
    float part_lo = 0.f,  part_hi = 0.f;

    for (int jt = 0; jt < NT; ++jt) {
        const int jb0 = jt * 128;
        const bool below = (jt < diag);
        const int nxt = jt + 1;

        // async prefetch of next B tile — overlaps GEMM + epilogue
        if (nxt < NT) {
            cp_tile16(gB + (size_t)nxt * 16384, sbase + OFF_B + (nxt & 1) * 16384, tid);
            cp_commit();
        }

        // zero-fill stores for fully-masked tiles
        if (below) {
            const float4 z = make_float4(0.f, 0.f, 0.f, 0.f);
            float* base = ob + (size_t)(it0 + wid * 16) * LEN + jb0 + lid * 4;
            #pragma unroll
            for (int r = 0; r < 16; ++r)
                *reinterpret_cast<float4*>(base + (size_t)r * LEN) = z;
        }

        float c[16][4];
        #pragma unroll
        for (int nb = 0; nb < 16; ++nb) {
            #pragma unroll
            for (int e = 0; e < 4; ++e) c[nb][e] = 0.f;
        }

        const unsigned bbuf = (unsigned)((jt & 1) * 16384);
        if (below) {
            // carry-only tile: single-pass fp16 (hi only)
            #pragma unroll
            for (int ks = 0; ks < 4; ++ks) {
                const unsigned bkb = ((unsigned)(ks * 32) + bkoff) ^ xk;
                #pragma unroll
                for (int np = 0; np < 8; ++np) {
                    unsigned b0, b1, b2, b3;
                    ldsm4(b_lane + bbuf + (unsigned)(np * 2048) + bkb, b0, b1, b2, b3);
                    mma16816(c[np * 2],     ah[ks][0], ah[ks][1], ah[ks][2], ah[ks][3], b0, b1);
                    mma16816(c[np * 2 + 1], ah[ks][0], ah[ks][1], ah[ks][2], ah[ks][3], b2, b3);
                }
            }
        } else {
            // visible tile: 2-pass fp16 split
            #pragma unroll
            for (int ks = 0; ks < 4; ++ks) {
                const unsigned bkb = ((unsigned)(ks * 32) + bkoff) ^ xk;
                #pragma unroll
                for (int np = 0; np < 8; ++np) {
                    unsigned b0, b1, b2, b3;
                    ldsm4(b_lane + bbuf + (unsigned)(np * 2048) + bkb, b0, b1, b2, b3);
                    mma16816(c[np * 2],     ah[ks][0], ah[ks][1], ah[ks][2], ah[ks][3], b0, b1);
                    mma16816(c[np * 2 + 1], ah[ks][0], ah[ks][1], ah[ks][2], ah[ks][3], b2, b3);
                    mma16816(c[np * 2],     al[ks][0], al[ks][1], al[ks][2], al[ks][3], b0, b1);
                    mma16816(c[np * 2 + 1], al[ks][0], al[ks][1], al[ks][2], al[ks][3], b2, b3);
                }
            }
        }

        // lane-partials -> full-row carry at the diagonal tile
        if (jt == diag) {
            float v = part_lo;
            v += __shfl_xor_sync(0xffffffffu, v, 1, 4);
            v += __shfl_xor_sync(0xffffffffu, v, 2, 4);
            carry_lo = v;
            v = part_hi;
            v += __shfl_xor_sync(0xffffffffu, v, 1, 4);
            v += __shfl_xor_sync(0xffffffffu, v, 2, 4);
            carry_hi = v;
        }

        auto scan_store = [&](int nb, bool masked) {
            const int col0 = jb0 + nb * 8 + q * 2;
            {
                float t0 = pow23(c[nb][0]);
                float t1 = pow23(c[nb][1]);
                float s = t0 + t1, p = s, o;
                o = __shfl_up_sync(0xffffffffu, p, 1, 4); if (q >= 1) p += o;
                o = __shfl_up_sync(0xffffffffu, p, 2, 4); if (q >= 2) p += o;
                float tot  = __shfl_sync(0xffffffffu, p, 3, 4);
                float excl = carry_lo + p - s;
                float o0 = excl + t0, o1 = excl + s;
                carry_lo += tot;
                float2 st = masked ? make_float2(col0 >= gi_lo ? o0 : 0.f,
                                                 col0 + 1 >= gi_lo ? o1 : 0.f)
                                   : make_float2(o0, o1);
                *reinterpret_cast<float2*>(row_lo + col0) = st;
            }
            {
                float t0 = pow23(c[nb][2]);
                float t1 = pow23(c[nb][3]);
                float s = t0 + t1, p = s, o;
                o = __shfl_up_sync(0xffffffffu, p, 1, 4); if (q >= 1) p += o;
                o = __shfl_up_sync(0xffffffffu, p, 2, 4); if (q >= 2) p += o;
                float tot  = __shfl_sync(0xffffffffu, p, 3, 4);
                float excl = carry_hi + p - s;
                float o0 = excl + t0, o1 = excl + s;
                carry_hi += tot;
                float2 st = masked ? make_float2(col0 >= gi_hi ? o0 : 0.f,
                                                 col0 + 1 >= gi_hi ? o1 : 0.f)
                                   : make_float2(o0, o1);
                *reinterpret_cast<float2*>(row_hi + col0) = st;
            }
        };

        auto accum_only = [&](int nb) {
            part_lo += pow23(c[nb][0]) + pow23(c[nb][1]);
            part_hi += pow23(c[nb][2]) + pow23(c[nb][3]);
        };

        if (below) {
            #pragma unroll
            for (int nb = 0; nb < 16; ++nb) accum_only(nb);
        } else if (jt == diag) {
            #pragma unroll
            for (int nb = 0; nb < 16; ++nb) scan_store(nb, true);
        } else {
            #pragma unroll
            for (int nb = 0; nb < 16; ++nb) scan_store(nb, false);
        }

        if (nxt < NT) cp_wait0();
        __syncthreads();
    }
}

extern "C" void kernel_launch(void* const* d_in, const int* in_sizes, int n_in,
                              void* d_out, int out_size) {
    const float* k   = (const float*)d_in[0];
    const float* src = (const float*)d_in[1];
    const float* dst = (const float*)d_in[2];
    float*       out = (float*)d_out;

    cudaFuncSetAttribute(mha_hmma6_kernel,
                         cudaFuncAttributeMaxDynamicSharedMemorySize, SMEM_TOTAL);
    (void)in_sizes; (void)n_in; (void)out_size;

    prep_kernel<<<BHN * LEN * 4 / 256, 256>>>(k, src, dst);
    dim3 grid(LEN / 64, BHN);
    mha_hmma6_kernel<<<grid, 128, SMEM_TOTAL>>>(out);
}

// round 11
// speedup vs baseline: 1.6007x; 1.0440x over previous
#include <cuda_runtime.h>
#include <cuda_fp16.h>

#define ERRF 1e-12f
constexpr int LEN = 2048;
constexpr int DIM = 64;
constexpr int NT  = 16;
constexpr int BHN = 32;

// Prepacked fp16 operands, row-major [bh][row][64], 128B per row.
__device__ __half g_Ah[BHN * LEN * DIM];   // k*sqrt(src)  hi
__device__ __half g_Al[BHN * LEN * DIM];   // k*sqrt(src)  lo
__device__ __half g_Bh[BHN * LEN * DIM];   // k*sqrt(dest) fp16

// smem: A hi @0 (8K), A lo @8K, B double-buffer @16K (2 x 16K)
constexpr int OFF_ALO = 8192;
constexpr int OFF_B   = 16384;
constexpr int SMEM_TOTAL = 49152;   // 48 KB -> 4 CTAs/SM

#define SWZ(o) ((o) ^ (((o) >> 3) & 0x70))

__device__ __forceinline__ unsigned smem_u32(const void* p) {
    return (unsigned)__cvta_generic_to_shared(p);
}
__device__ __forceinline__ float fast_lg2(float x) { float y; asm("lg2.approx.f32 %0, %1;" : "=f"(y) : "f"(x)); return y; }
__device__ __forceinline__ float fast_ex2(float x) { float y; asm("ex2.approx.f32 %0, %1;" : "=f"(y) : "f"(x)); return y; }
// relu(x)+eps == max(x,eps) except on x in (0,eps): one op fewer
__device__ __forceinline__ float pow23(float x) {
    return fast_ex2(fast_lg2(fmaxf(x, ERRF)) * 0.66666667f);
}

__device__ __forceinline__ void ldsm4(unsigned addr, unsigned& r0, unsigned& r1, unsigned& r2, unsigned& r3) {
    asm volatile("ldmatrix.sync.aligned.m8n8.x4.shared.b16 {%0,%1,%2,%3}, [%4];"
                 : "=r"(r0), "=r"(r1), "=r"(r2), "=r"(r3) : "r"(addr));
}

__device__ __forceinline__ void mma16816(float* c, unsigned a0, unsigned a1, unsigned a2, unsigned a3,
                                         unsigned b0, unsigned b1) {
    asm volatile("mma.sync.aligned.m16n8k16.row.col.f32.f16.f16.f32 "
                 "{%0,%1,%2,%3}, {%4,%5,%6,%7}, {%8,%9}, {%0,%1,%2,%3};"
                 : "+f"(c[0]), "+f"(c[1]), "+f"(c[2]), "+f"(c[3])
                 : "r"(a0), "r"(a1), "r"(a2), "r"(a3), "r"(b0), "r"(b1));
}
// first k-slice: C = A*B + 0 (no accumulator pre-init needed)
__device__ __forceinline__ void mma16816_z(float* c, unsigned a0, unsigned a1, unsigned a2, unsigned a3,
                                           unsigned b0, unsigned b1) {
    asm volatile("mma.sync.aligned.m16n8k16.row.col.f32.f16.f16.f32 "
                 "{%0,%1,%2,%3}, {%4,%5,%6,%7}, {%8,%9}, {%10,%10,%10,%10};"
                 : "=f"(c[0]), "=f"(c[1]), "=f"(c[2]), "=f"(c[3])
                 : "r"(a0), "r"(a1), "r"(a2), "r"(a3), "r"(b0), "r"(b1), "f"(0.f));
}

__device__ __forceinline__ void cp16(unsigned sdst, const void* gsrc) {
    asm volatile("cp.async.cg.shared.global [%0], [%1], 16;" :: "r"(sdst), "l"(gsrc) : "memory");
}
__device__ __forceinline__ void cp_commit() { asm volatile("cp.async.commit_group;" ::: "memory"); }
__device__ __forceinline__ void cp_wait0()  { asm volatile("cp.async.wait_group 0;" ::: "memory"); }

__device__ __forceinline__ void stcs2(float* p, float2 v) {
    asm volatile("st.global.cs.v2.f32 [%0], {%1, %2};" :: "l"(p), "f"(v.x), "f"(v.y) : "memory");
}
__device__ __forceinline__ void stcs4_zero(float* p) {
    asm volatile("st.global.cs.v4.f32 [%0], {%1, %1, %1, %1};" :: "l"(p), "f"(0.f) : "memory");
}

// ---------------- prep kernel: fp32 -> scaled fp16 hi/lo ----------------
__global__ void __launch_bounds__(256)
prep_kernel(const float* __restrict__ k, const float* __restrict__ src,
            const float* __restrict__ dst)
{
    const int idx = blockIdx.x * 256 + threadIdx.x;
    const int row = idx >> 2;
    const int q   = idx & 3;
    const float ws = sqrtf(src[row] + ERRF);
    const float wd = sqrtf(dst[row] + ERRF);
    const float4* kp = reinterpret_cast<const float4*>(k + (size_t)row * DIM + q * 16);

    __half2 oh[8], ol[8], ob[8];
    #pragma unroll
    for (int p = 0; p < 4; ++p) {
        float4 v = kp[p];
        float a0 = v.x * ws, a1 = v.y * ws, a2 = v.z * ws, a3 = v.w * ws;
        __half h0 = __float2half_rn(a0), h1 = __float2half_rn(a1);
        __half h2 = __float2half_rn(a2), h3 = __float2half_rn(a3);
        oh[p * 2]     = __half2(h0, h1);
        oh[p * 2 + 1] = __half2(h2, h3);
        ol[p * 2]     = __floats2half2_rn(a0 - __half2float(h0), a1 - __half2float(h1));
        ol[p * 2 + 1] = __floats2half2_rn(a2 - __half2float(h2), a3 - __half2float(h3));
        ob[p * 2]     = __floats2half2_rn(v.x * wd, v.y * wd);
        ob[p * 2 + 1] = __floats2half2_rn(v.z * wd, v.w * wd);
    }
    const size_t o = (size_t)row * DIM + q * 16;
    uint4* dAh = reinterpret_cast<uint4*>(g_Ah + o);
    uint4* dAl = reinterpret_cast<uint4*>(g_Al + o);
    uint4* dBh = reinterpret_cast<uint4*>(g_Bh + o);
    const uint4* sh = reinterpret_cast<const uint4*>(oh);
    const uint4* sl = reinterpret_cast<const uint4*>(ol);
    const uint4* sb = reinterpret_cast<const uint4*>(ob);
    dAh[0] = sh[0]; dAh[1] = sh[1];
    dAl[0] = sl[0]; dAl[1] = sl[1];
    dBh[0] = sb[0]; dBh[1] = sb[1];
}

// copy one 16KB B tile GMEM -> swizzled SMEM via cp.async (128 threads)
__device__ __forceinline__ void cp_tile16(const char* gsrc, unsigned sdst, int tid) {
    #pragma unroll
    for (int i = 0; i < 8; ++i) {
        int cid = tid + 128 * i;
        unsigned off = (unsigned)(cid << 4);
        cp16(sdst + SWZ(off), gsrc + off);
    }
}
// copy one 8KB A tile (64 rows) GMEM -> swizzled SMEM
__device__ __forceinline__ void cp_tile8(const char* gsrc, unsigned sdst, int tid) {
    #pragma unroll
    for (int i = 0; i < 4; ++i) {
        int cid = tid + 128 * i;
        unsigned off = (unsigned)(cid << 4);
        cp16(sdst + SWZ(off), gsrc + off);
    }
}

// ---------------- main kernel: 128 threads, 64-row i-tile ----------------
__global__ void __launch_bounds__(128, 4)
mha_hmma7_kernel(float* __restrict__ out)
{
    extern __shared__ char smem[];
    const int tid = threadIdx.x;
    const int wid = tid >> 5;
    const int lid = tid & 31;
    const int bh  = blockIdx.y;
    const int diag = blockIdx.x >> 1;
    const int it0 = blockIdx.x * 64;

    float* ob = out + (size_t)bh * LEN * LEN;
    const char* gA  = reinterpret_cast<const char*>(g_Ah + ((size_t)bh * LEN + it0) * DIM);
    const char* gAl = reinterpret_cast<const char*>(g_Al + ((size_t)bh * LEN + it0) * DIM);
    const char* gB  = reinterpret_cast<const char*>(g_Bh + (size_t)bh * LEN * DIM);

    const unsigned sbase = smem_u32(smem);

    cp_tile8(gA,  sbase, tid);
    cp_tile8(gAl, sbase + OFF_ALO, tid);
    cp_tile16(gB, sbase + OFF_B, tid);
    cp_commit();
    cp_wait0();
    __syncthreads();

    // ldmatrix lane addressing
    const int l7  = lid & 7;
    const int sel = lid >> 3;
    const unsigned xk = (unsigned)(l7 << 4);
    const int arow  = wid * 16 + l7 + ((sel & 1) ? 8 : 0);
    const unsigned akoff = (sel & 2) ? 16u : 0u;
    const int bn    = l7 + ((sel & 2) ? 8 : 0);
    const unsigned bkoff = (sel & 1) ? 16u : 0u;
    const unsigned a_lane = sbase + (unsigned)(arow * 128);
    const unsigned b_lane = sbase + OFF_B + (unsigned)(bn * 128);

    // A fragments register-resident
    unsigned ah[4][4], al[4][4];
    #pragma unroll
    for (int ks = 0; ks < 4; ++ks) {
        const unsigned ak = ((unsigned)(ks * 32) + akoff) ^ xk;
        ldsm4(a_lane + ak, ah[ks][0], ah[ks][1], ah[ks][2], ah[ks][3]);
        ldsm4(a_lane + OFF_ALO + ak, al[ks][0], al[ks][1], al[ks][2], al[ks][3]);
    }

    // epilogue lane mapping
    const int q  = lid & 3;
    const int g4 = lid >> 2;
    const int gi_lo = it0 + wid * 16 + g4;
    const int gi_hi = gi_lo + 8;
    float* const row_lo = ob + (size_t)gi_lo * LEN;
    float* const row_hi = ob + (size_t)gi_hi * LEN;

    float carry_lo = 0.f, carry_hi = 0.f;
    float part_lo = 0.f,  part_hi = 0.f;

    for (int jt = 0; jt < NT; ++jt) {
        const int jb0 = jt * 128;
        const bool below = (jt < diag);
        const int nxt = jt + 1;

        if (nxt < NT) {
            cp_tile16(gB + (size_t)nxt * 16384, sbase + OFF_B + (nxt & 1) * 16384, tid);
            cp_commit();
        }

        // zero-fill stores for fully-masked tiles (streaming)
        if (below) {
            float* base = ob + (size_t)(it0 + wid * 16) * LEN + jb0 + lid * 4;
            #pragma unroll
            for (int r = 0; r < 16; ++r)
                stcs4_zero(base + (size_t)r * LEN);
        }

        float c[16][4];
        const unsigned bbuf = (unsigned)((jt & 1) * 16384);
        if (below) {
            // carry-only tile: single-pass fp16 (hi only)
            #pragma unroll
            for (int ks = 0; ks < 4; ++ks) {
                const unsigned bkb = ((unsigned)(ks * 32) + bkoff) ^ xk;
                #pragma unroll
                for (int np = 0; np < 8; ++np) {
                    unsigned b0, b1, b2, b3;
                    ldsm4(b_lane + bbuf + (unsigned)(np * 2048) + bkb, b0, b1, b2, b3);
                    if (ks == 0) {
                        mma16816_z(c[np * 2],     ah[0][0], ah[0][1], ah[0][2], ah[0][3], b0, b1);
                        mma16816_z(c[np * 2 + 1], ah[0][0], ah[0][1], ah[0][2], ah[0][3], b2, b3);
                    } else {
                        mma16816(c[np * 2],     ah[ks][0], ah[ks][1], ah[ks][2], ah[ks][3], b0, b1);
                        mma16816(c[np * 2 + 1], ah[ks][0], ah[ks][1], ah[ks][2], ah[ks][3], b2, b3);
                    }
                }
            }
        } else {
            // visible tile: 2-pass fp16 split
            #pragma unroll
            for (int ks = 0; ks < 4; ++ks) {
                const unsigned bkb = ((unsigned)(ks * 32) + bkoff) ^ xk;
                #pragma unroll
                for (int np = 0; np < 8; ++np) {
                    unsigned b0, b1, b2, b3;
                    ldsm4(b_lane + bbuf + (unsigned)(np * 2048) + bkb, b0, b1, b2, b3);
                    if (ks == 0) {
                        mma16816_z(c[np * 2],     ah[0][0], ah[0][1], ah[0][2], ah[0][3], b0, b1);
                        mma16816_z(c[np * 2 + 1], ah[0][0], ah[0][1], ah[0][2], ah[0][3], b2, b3);
                    } else {
                        mma16816(c[np * 2],     ah[ks][0], ah[ks][1], ah[ks][2], ah[ks][3], b0, b1);
                        mma16816(c[np * 2 + 1], ah[ks][0], ah[ks][1], ah[ks][2], ah[ks][3], b2, b3);
                    }
                    mma16816(c[np * 2],     al[ks][0], al[ks][1], al[ks][2], al[ks][3], b0, b1);
                    mma16816(c[np * 2 + 1], al[ks][0], al[ks][1], al[ks][2], al[ks][3], b2, b3);
                }
            }
        }

        // lane-partials -> full-row carry at the diagonal tile
        if (jt == diag) {
            float v = part_lo;
            v += __shfl_xor_sync(0xffffffffu, v, 1, 4);
            v += __shfl_xor_sync(0xffffffffu, v, 2, 4);
            carry_lo = v;
            v = part_hi;
            v += __shfl_xor_sync(0xffffffffu, v, 1, 4);
            v += __shfl_xor_sync(0xffffffffu, v, 2, 4);
            carry_hi = v;
        }

        auto scan_store = [&](int nb, bool masked) {
            const int col0 = jb0 + nb * 8 + q * 2;
            {
                float t0 = pow23(c[nb][0]);
                float t1 = pow23(c[nb][1]);
                float s = t0 + t1, p = s, o;
                o = __shfl_up_sync(0xffffffffu, p, 1, 4); if (q >= 1) p += o;
                o = __shfl_up_sync(0xffffffffu, p, 2, 4); if (q >= 2) p += o;
                float tot  = __shfl_sync(0xffffffffu, p, 3, 4);
                float excl = carry_lo + p - s;
                float o0 = excl + t0, o1 = excl + s;
                carry_lo += tot;
                float2 st = masked ? make_float2(col0 >= gi_lo ? o0 : 0.f,
                                                 col0 + 1 >= gi_lo ? o1 : 0.f)
                                   : make_float2(o0, o1);
                stcs2(row_lo + col0, st);
            }
            {
                float t0 = pow23(c[nb][2]);
                float t1 = pow23(c[nb][3]);
                float s = t0 + t1, p = s, o;
                o = __shfl_up_sync(0xffffffffu, p, 1, 4); if (q >= 1) p += o;
                o = __shfl_up_sync(0xffffffffu, p, 2, 4); if (q >= 2) p += o;
                float tot  = __shfl_sync(0xffffffffu, p, 3, 4);
                float excl = carry_hi + p - s;
                float o0 = excl + t0, o1 = excl + s;
                carry_hi += tot;
                float2 st = masked ? make_float2(col0 >= gi_hi ? o0 : 0.f,
                                                 col0 + 1 >= gi_hi ? o1 : 0.f)
                                   : make_float2(o0, o1);
                stcs2(row_hi + col0, st);
            }
        };

        auto accum_only = [&](int nb) {
            part_lo += pow23(c[nb][0]) + pow23(c[nb][1]);
            part_hi += pow23(c[nb][2]) + pow23(c[nb][3]);
        };

        if (below) {
            #pragma unroll
            for (int nb = 0; nb < 16; ++nb) accum_only(nb);
        } else if (jt == diag) {
            #pragma unroll
            for (int nb = 0; nb < 16; ++nb) scan_store(nb, true);
        } else {
            #pragma unroll
            for (int nb = 0; nb < 16; ++nb) scan_store(nb, false);
        }

        if (nxt < NT) cp_wait0();
        __syncthreads();
    }
}

extern "C" void kernel_launch(void* const* d_in, const int* in_sizes, int n_in,
                              void* d_out, int out_size) {
    const float* k   = (const float*)d_in[0];
    const float* src = (const float*)d_in[1];
    const float* dst = (const float*)d_in[2];
    float*       out = (float*)d_out;

    cudaFuncSetAttribute(mha_hmma7_kernel,
                         cudaFuncAttributeMaxDynamicSharedMemorySize, SMEM_TOTAL);
    (void)in_sizes; (void)n_in; (void)out_size;

    prep_kernel<<<BHN * LEN * 4 / 256, 256>>>(k, src, dst);
    dim3 grid(LEN / 64, BHN);
    mha_hmma7_kernel<<<grid, 128, SMEM_TOTAL>>>(out);
}

// round 12
// speedup vs baseline: 1.7100x; 1.0683x over previous
#include <cuda_runtime.h>
#include <cuda_fp16.h>

#define ERRF 1e-12f
constexpr int LEN = 2048;
constexpr int DIM = 64;
constexpr int NT  = 16;
constexpr int BHN = 32;

// Prepacked fp16 operands, row-major [bh][row][64], 128B per row.
__device__ __half g_Ah[BHN * LEN * DIM];   // k*sqrt(src)  hi
__device__ __half g_Al[BHN * LEN * DIM];   // k*sqrt(src)  lo
__device__ __half g_Bh[BHN * LEN * DIM];   // k*sqrt(dest) fp16

// smem: A hi @0 (8K), A lo @8K, B double-buffer @16K (2 x 16K)
constexpr int OFF_ALO = 8192;
constexpr int OFF_B   = 16384;
constexpr int SMEM_TOTAL = 49152;   // 48 KB -> 4 CTAs/SM

#define SWZ(o) ((o) ^ (((o) >> 3) & 0x70))

__device__ __forceinline__ unsigned smem_u32(const void* p) {
    return (unsigned)__cvta_generic_to_shared(p);
}
__device__ __forceinline__ float fast_lg2(float x) { float y; asm("lg2.approx.f32 %0, %1;" : "=f"(y) : "f"(x)); return y; }
__device__ __forceinline__ float fast_ex2(float x) { float y; asm("ex2.approx.f32 %0, %1;" : "=f"(y) : "f"(x)); return y; }
// relu(x)+eps == max(x,eps) except on x in (0,eps): one op fewer
__device__ __forceinline__ float pow23(float x) {
    return fast_ex2(fast_lg2(fmaxf(x, ERRF)) * 0.66666667f);
}

__device__ __forceinline__ void ldsm4(unsigned addr, unsigned& r0, unsigned& r1, unsigned& r2, unsigned& r3) {
    asm volatile("ldmatrix.sync.aligned.m8n8.x4.shared.b16 {%0,%1,%2,%3}, [%4];"
                 : "=r"(r0), "=r"(r1), "=r"(r2), "=r"(r3) : "r"(addr));
}

__device__ __forceinline__ void mma16816(float* c, unsigned a0, unsigned a1, unsigned a2, unsigned a3,
                                         unsigned b0, unsigned b1) {
    asm volatile("mma.sync.aligned.m16n8k16.row.col.f32.f16.f16.f32 "
                 "{%0,%1,%2,%3}, {%4,%5,%6,%7}, {%8,%9}, {%0,%1,%2,%3};"
                 : "+f"(c[0]), "+f"(c[1]), "+f"(c[2]), "+f"(c[3])
                 : "r"(a0), "r"(a1), "r"(a2), "r"(a3), "r"(b0), "r"(b1));
}
// first k-slice: C = A*B + 0
__device__ __forceinline__ void mma16816_z(float* c, unsigned a0, unsigned a1, unsigned a2, unsigned a3,
                                           unsigned b0, unsigned b1) {
    asm volatile("mma.sync.aligned.m16n8k16.row.col.f32.f16.f16.f32 "
                 "{%0,%1,%2,%3}, {%4,%5,%6,%7}, {%8,%9}, {%10,%10,%10,%10};"
                 : "=f"(c[0]), "=f"(c[1]), "=f"(c[2]), "=f"(c[3])
                 : "r"(a0), "r"(a1), "r"(a2), "r"(a3), "r"(b0), "r"(b1), "f"(0.f));
}

__device__ __forceinline__ void cp16(unsigned sdst, const void* gsrc) {
    asm volatile("cp.async.cg.shared.global [%0], [%1], 16;" :: "r"(sdst), "l"(gsrc) : "memory");
}
__device__ __forceinline__ void cp_commit() { asm volatile("cp.async.commit_group;" ::: "memory"); }
__device__ __forceinline__ void cp_wait0()  { asm volatile("cp.async.wait_group 0;" ::: "memory"); }

__device__ __forceinline__ void stcs4(float* p, float4 v) {
    asm volatile("st.global.cs.v4.f32 [%0], {%1,%2,%3,%4};"
                 :: "l"(p), "f"(v.x), "f"(v.y), "f"(v.z), "f"(v.w) : "memory");
}
__device__ __forceinline__ void stcs4_zero(float* p) {
    asm volatile("st.global.cs.v4.f32 [%0], {%1, %1, %1, %1};" :: "l"(p), "f"(0.f) : "memory");
}

// ---------------- prep kernel: fp32 -> scaled fp16 hi/lo ----------------
__global__ void __launch_bounds__(256)
prep_kernel(const float* __restrict__ k, const float* __restrict__ src,
            const float* __restrict__ dst)
{
    const int idx = blockIdx.x * 256 + threadIdx.x;
    const int row = idx >> 2;
    const int q   = idx & 3;
    const float ws = sqrtf(src[row] + ERRF);
    const float wd = sqrtf(dst[row] + ERRF);
    const float4* kp = reinterpret_cast<const float4*>(k + (size_t)row * DIM + q * 16);

    __half2 oh[8], ol[8], ob[8];
    #pragma unroll
    for (int p = 0; p < 4; ++p) {
        float4 v = kp[p];
        float a0 = v.x * ws, a1 = v.y * ws, a2 = v.z * ws, a3 = v.w * ws;
        __half h0 = __float2half_rn(a0), h1 = __float2half_rn(a1);
        __half h2 = __float2half_rn(a2), h3 = __float2half_rn(a3);
        oh[p * 2]     = __half2(h0, h1);
        oh[p * 2 + 1] = __half2(h2, h3);
        ol[p * 2]     = __floats2half2_rn(a0 - __half2float(h0), a1 - __half2float(h1));
        ol[p * 2 + 1] = __floats2half2_rn(a2 - __half2float(h2), a3 - __half2float(h3));
        ob[p * 2]     = __floats2half2_rn(v.x * wd, v.y * wd);
        ob[p * 2 + 1] = __floats2half2_rn(v.z * wd, v.w * wd);
    }
    const size_t o = (size_t)row * DIM + q * 16;
    uint4* dAh = reinterpret_cast<uint4*>(g_Ah + o);
    uint4* dAl = reinterpret_cast<uint4*>(g_Al + o);
    uint4* dBh = reinterpret_cast<uint4*>(g_Bh + o);
    const uint4* sh = reinterpret_cast<const uint4*>(oh);
    const uint4* sl = reinterpret_cast<const uint4*>(ol);
    const uint4* sb = reinterpret_cast<const uint4*>(ob);
    dAh[0] = sh[0]; dAh[1] = sh[1];
    dAl[0] = sl[0]; dAl[1] = sl[1];
    dBh[0] = sb[0]; dBh[1] = sb[1];
}

// B tile copy with column-coalescing row permutation:
// within each 16-row group, true row t -> position [0,1,8,9,2,3,10,11,4,5,12,13,6,7,14,15]
__device__ __forceinline__ void cp_tile16_perm(const char* gsrc, unsigned sdst, int tid) {
    #pragma unroll
    for (int i = 0; i < 8; ++i) {
        int cid = tid + 128 * i;            // 0..1023 ; row = cid>>3, 16B chunk = cid&7
        int row = cid >> 3;
        int pr  = (row & ~15) | ((row & 2) << 2) | ((row >> 1) & 6) | (row & 1);
        unsigned dst = (unsigned)(pr * 128 + (cid & 7) * 16);
        cp16(sdst + SWZ(dst), gsrc + (unsigned)(cid << 4));
    }
}
// A tile (8KB, 64 rows), no permutation
__device__ __forceinline__ void cp_tile8(const char* gsrc, unsigned sdst, int tid) {
    #pragma unroll
    for (int i = 0; i < 4; ++i) {
        int cid = tid + 128 * i;
        unsigned off = (unsigned)(cid << 4);
        cp16(sdst + SWZ(off), gsrc + off);
    }
}

// ---------------- main kernel: 128 threads, 64-row i-tile ----------------
__global__ void __launch_bounds__(128, 4)
mha_hmma8_kernel(float* __restrict__ out)
{
    extern __shared__ char smem[];
    const int tid = threadIdx.x;
    const int wid = tid >> 5;
    const int lid = tid & 31;
    const int bh  = blockIdx.y;
    const int diag = blockIdx.x >> 1;
    const int it0 = blockIdx.x * 64;

    float* ob = out + (size_t)bh * LEN * LEN;
    const char* gA  = reinterpret_cast<const char*>(g_Ah + ((size_t)bh * LEN + it0) * DIM);
    const char* gAl = reinterpret_cast<const char*>(g_Al + ((size_t)bh * LEN + it0) * DIM);
    const char* gB  = reinterpret_cast<const char*>(g_Bh + (size_t)bh * LEN * DIM);

    const unsigned sbase = smem_u32(smem);

    cp_tile8(gA,  sbase, tid);
    cp_tile8(gAl, sbase + OFF_ALO, tid);
    cp_tile16_perm(gB, sbase + OFF_B, tid);
    cp_commit();
    cp_wait0();
    __syncthreads();

    // ldmatrix lane addressing
    const int l7  = lid & 7;
    const int sel = lid >> 3;
    const unsigned xk = (unsigned)(l7 << 4);
    const int arow  = wid * 16 + l7 + ((sel & 1) ? 8 : 0);
    const unsigned akoff = (sel & 2) ? 16u : 0u;
    const int bn    = l7 + ((sel & 2) ? 8 : 0);
    const unsigned bkoff = (sel & 1) ? 16u : 0u;
    const unsigned a_lane = sbase + (unsigned)(arow * 128);
    const unsigned b_lane = sbase + OFF_B + (unsigned)(bn * 128);

    // A fragments register-resident
    unsigned ah[4][4], al[4][4];
    #pragma unroll
    for (int ks = 0; ks < 4; ++ks) {
        const unsigned ak = ((unsigned)(ks * 32) + akoff) ^ xk;
        ldsm4(a_lane + ak, ah[ks][0], ah[ks][1], ah[ks][2], ah[ks][3]);
        ldsm4(a_lane + OFF_ALO + ak, al[ks][0], al[ks][1], al[ks][2], al[ks][3]);
    }

    // epilogue lane mapping: with the B permutation, for fragment pair (2m, 2m+1)
    // lane q owns TRUE cols 16m + 4q .. 16m + 4q + 3
    const int q  = lid & 3;
    const int g4 = lid >> 2;
    const int gi_lo = it0 + wid * 16 + g4;
    const int gi_hi = gi_lo + 8;
    float* const row_lo = ob + (size_t)gi_lo * LEN;
    float* const row_hi = ob + (size_t)gi_hi * LEN;

    float carry_lo = 0.f, carry_hi = 0.f;
    float part_lo = 0.f,  part_hi = 0.f;

    for (int jt = 0; jt < NT; ++jt) {
        const int jb0 = jt * 128;
        const bool below = (jt < diag);
        const int nxt = jt + 1;

        if (nxt < NT) {
            cp_tile16_perm(gB + (size_t)nxt * 16384, sbase + OFF_B + (nxt & 1) * 16384, tid);
            cp_commit();
        }

        // zero-fill stores for fully-masked tiles (streaming, row-contiguous)
        if (below) {
            float* base = ob + (size_t)(it0 + wid * 16) * LEN + jb0 + lid * 4;
            #pragma unroll
            for (int r = 0; r < 16; ++r)
                stcs4_zero(base + (size_t)r * LEN);
        }

        float c[16][4];
        const unsigned bbuf = (unsigned)((jt & 1) * 16384);
        if (below) {
            #pragma unroll
            for (int ks = 0; ks < 4; ++ks) {
                const unsigned bkb = ((unsigned)(ks * 32) + bkoff) ^ xk;
                #pragma unroll
                for (int np = 0; np < 8; ++np) {
                    unsigned b0, b1, b2, b3;
                    ldsm4(b_lane + bbuf + (unsigned)(np * 2048) + bkb, b0, b1, b2, b3);
                    if (ks == 0) {
                        mma16816_z(c[np * 2],     ah[0][0], ah[0][1], ah[0][2], ah[0][3], b0, b1);
                        mma16816_z(c[np * 2 + 1], ah[0][0], ah[0][1], ah[0][2], ah[0][3], b2, b3);
                    } else {
                        mma16816(c[np * 2],     ah[ks][0], ah[ks][1], ah[ks][2], ah[ks][3], b0, b1);
                        mma16816(c[np * 2 + 1], ah[ks][0], ah[ks][1], ah[ks][2], ah[ks][3], b2, b3);
                    }
                }
            }
        } else {
            #pragma unroll
            for (int ks = 0; ks < 4; ++ks) {
                const unsigned bkb = ((unsigned)(ks * 32) + bkoff) ^ xk;
                #pragma unroll
                for (int np = 0; np < 8; ++np) {
                    unsigned b0, b1, b2, b3;
                    ldsm4(b_lane + bbuf + (unsigned)(np * 2048) + bkb, b0, b1, b2, b3);
                    if (ks == 0) {
                        mma16816_z(c[np * 2],     ah[0][0], ah[0][1], ah[0][2], ah[0][3], b0, b1);
                        mma16816_z(c[np * 2 + 1], ah[0][0], ah[0][1], ah[0][2], ah[0][3], b2, b3);
                    } else {
                        mma16816(c[np * 2],     ah[ks][0], ah[ks][1], ah[ks][2], ah[ks][3], b0, b1);
                        mma16816(c[np * 2 + 1], ah[ks][0], ah[ks][1], ah[ks][2], ah[ks][3], b2, b3);
                    }
                    mma16816(c[np * 2],     al[ks][0], al[ks][1], al[ks][2], al[ks][3], b0, b1);
                    mma16816(c[np * 2 + 1], al[ks][0], al[ks][1], al[ks][2], al[ks][3], b2, b3);
                }
            }
        }

        // lane-partials -> full-row carry at the diagonal tile
        if (jt == diag) {
            float v = part_lo;
            v += __shfl_xor_sync(0xffffffffu, v, 1, 4);
            v += __shfl_xor_sync(0xffffffffu, v, 2, 4);
            carry_lo = v;
            v = part_hi;
            v += __shfl_xor_sync(0xffffffffu, v, 1, 4);
            v += __shfl_xor_sync(0xffffffffu, v, 2, 4);
            carry_hi = v;
        }

        // one scan per 16-col fragment pair; lane q stores 4 consecutive cols
        auto scan_store4 = [&](int m, bool masked) {
            const int col0 = jb0 + m * 16 + q * 4;
            {
                float t0 = pow23(c[2 * m][0]);
                float t1 = pow23(c[2 * m][1]);
                float t2 = pow23(c[2 * m + 1][0]);
                float t3 = pow23(c[2 * m + 1][1]);
                float s = t0 + t1 + t2 + t3, p = s, o;
                o = __shfl_up_sync(0xffffffffu, p, 1, 4); if (q >= 1) p += o;
                o = __shfl_up_sync(0xffffffffu, p, 2, 4); if (q >= 2) p += o;
                float tot = __shfl_sync(0xffffffffu, p, 3, 4);
                float e = carry_lo + (p - s);
                float o0 = e + t0, o1 = o0 + t1, o2 = o1 + t2, o3 = o2 + t3;
                carry_lo += tot;
                float4 st = masked ? make_float4(col0 >= gi_lo ? o0 : 0.f,
                                                 col0 + 1 >= gi_lo ? o1 : 0.f,
                                                 col0 + 2 >= gi_lo ? o2 : 0.f,
                                                 col0 + 3 >= gi_lo ? o3 : 0.f)
                                   : make_float4(o0, o1, o2, o3);
                stcs4(row_lo + col0, st);
            }
            {
                float t0 = pow23(c[2 * m][2]);
                float t1 = pow23(c[2 * m][3]);
                float t2 = pow23(c[2 * m + 1][2]);
                float t3 = pow23(c[2 * m + 1][3]);
                float s = t0 + t1 + t2 + t3, p = s, o;
                o = __shfl_up_sync(0xffffffffu, p, 1, 4); if (q >= 1) p += o;
                o = __shfl_up_sync(0xffffffffu, p, 2, 4); if (q >= 2) p += o;
                float tot = __shfl_sync(0xffffffffu, p, 3, 4);
                float e = carry_hi + (p - s);
                float o0 = e + t0, o1 = o0 + t1, o2 = o1 + t2, o3 = o2 + t3;
                carry_hi += tot;
                float4 st = masked ? make_float4(col0 >= gi_hi ? o0 : 0.f,
                                                 col0 + 1 >= gi_hi ? o1 : 0.f,
                                                 col0 + 2 >= gi_hi ? o2 : 0.f,
                                                 col0 + 3 >= gi_hi ? o3 : 0.f)
                                   : make_float4(o0, o1, o2, o3);
                stcs4(row_hi + col0, st);
            }
        };

        auto accum_only = [&](int nb) {
            part_lo += pow23(c[nb][0]) + pow23(c[nb][1]);
            part_hi += pow23(c[nb][2]) + pow23(c[nb][3]);
        };

        if (below) {
            #pragma unroll
            for (int nb = 0; nb < 16; ++nb) accum_only(nb);
        } else if (jt == diag) {
            #pragma unroll
            for (int m = 0; m < 8; ++m) scan_store4(m, true);
        } else {
            #pragma unroll
            for (int m = 0; m < 8; ++m) scan_store4(m, false);
        }

        if (nxt < NT) cp_wait0();
        __syncthreads();
    }
}

extern "C" void kernel_launch(void* const* d_in, const int* in_sizes, int n_in,
                              void* d_out, int out_size) {
    const float* k   = (const float*)d_in[0];
    const float* src = (const float*)d_in[1];
    const float* dst = (const float*)d_in[2];
    float*       out = (float*)d_out;

    cudaFuncSetAttribute(mha_hmma8_kernel,
                         cudaFuncAttributeMaxDynamicSharedMemorySize, SMEM_TOTAL);
    (void)in_sizes; (void)n_in; (void)out_size;

    prep_kernel<<<BHN * LEN * 4 / 256, 256>>>(k, src, dst);
    dim3 grid(LEN / 64, BHN);
    mha_hmma8_kernel<<<grid, 128, SMEM_TOTAL>>>(out);
}